// round 15
// baseline (speedup 1.0000x reference)
#include <cuda_runtime.h>
#include <cuda_fp16.h>
#include <cstdint>

#define D_MODEL 1024
#define S_LEN   2048
#define NB      2
#define NH      16
#define HD      64
#define DQK     128
#define BHN     (NB*NH)
#define LOG2E   1.44269504088896340736f

// Scratch (allocation-free rule: __device__ globals)
__device__ __half g_xh [(size_t)NB * S_LEN * D_MODEL];
__device__ __half g_Wqh[D_MODEL * D_MODEL];
__device__ __half g_Wkh[D_MODEL * D_MODEL];
__device__ __half g_Wvh[D_MODEL * D_MODEL];
__device__ __half g_Woh[D_MODEL * D_MODEL];
__device__ __half g_Jth[NH * HD * HD];              // [h][e][d] = lam*log2e * J[h][d][e]
__device__ __half g_Qh[(size_t)BHN * S_LEN * DQK];  // [0:64]=Q*(log2e/8), [64:128]=lam*log2e*tanh(Q)@J
__device__ __half g_Kh[(size_t)BHN * S_LEN * DQK];  // [0:64]=K,   [64:128]=tanh(K)
__device__ __half g_Vh[(size_t)BHN * S_LEN * HD];
__device__ __half g_attnh[(size_t)NB * S_LEN * D_MODEL];

__device__ __forceinline__ void mma_f16(float* c, const uint32_t* a, const uint32_t* b) {
    asm volatile(
        "mma.sync.aligned.m16n8k16.row.col.f32.f16.f16.f32 "
        "{%0,%1,%2,%3}, {%4,%5,%6,%7}, {%8,%9}, {%0,%1,%2,%3};"
        : "+f"(c[0]), "+f"(c[1]), "+f"(c[2]), "+f"(c[3])
        : "r"(a[0]), "r"(a[1]), "r"(a[2]), "r"(a[3]), "r"(b[0]), "r"(b[1]));
}

__device__ __forceinline__ uint32_t packh2(float x, float y) {
    __half2 h = __floats2half2_rn(x, y);
    return *reinterpret_cast<uint32_t*>(&h);
}

__device__ __forceinline__ uint32_t smaddr(const void* p) {
    uint32_t a;
    asm("{ .reg .u64 t; cvta.to.shared.u64 t, %1; cvt.u32.u64 %0, t; }"
        : "=r"(a) : "l"(p));
    return a;
}

__device__ __forceinline__ void ldsm_x4(uint32_t& r0, uint32_t& r1, uint32_t& r2,
                                        uint32_t& r3, uint32_t addr) {
    asm volatile("ldmatrix.sync.aligned.m8n8.x4.shared.b16 {%0,%1,%2,%3}, [%4];"
                 : "=r"(r0), "=r"(r1), "=r"(r2), "=r"(r3) : "r"(addr));
}

__device__ __forceinline__ void ldsm_x4_t(uint32_t& r0, uint32_t& r1, uint32_t& r2,
                                          uint32_t& r3, uint32_t addr) {
    asm volatile("ldmatrix.sync.aligned.m8n8.x4.trans.shared.b16 {%0,%1,%2,%3}, [%4];"
                 : "=r"(r0), "=r"(r1), "=r"(r2), "=r"(r3) : "r"(addr));
}

#define CP_ASYNC16(s, g) \
    asm volatile("cp.async.cg.shared.global [%0], [%1], 16;" :: "r"(s), "l"(g))
#define CP_COMMIT() asm volatile("cp.async.commit_group;")
#define CP_WAIT0()  asm volatile("cp.async.wait_group 0;")
#define CP_WAIT1()  asm volatile("cp.async.wait_group 1;")

// ---------------------------------------------------------------------------
// convert: fp32 inputs -> fp16 scratch; Jt[h][e][d] = lam*log2e * J[h][d][e]
// ---------------------------------------------------------------------------
__global__ void convert_kernel(
    const float* __restrict__ x,
    const float* __restrict__ Wq, const float* __restrict__ Wk,
    const float* __restrict__ Wv, const float* __restrict__ Wo,
    const float* __restrict__ J,  const float* __restrict__ lam_p)
{
    const int g = blockIdx.x * blockDim.x + threadIdx.x;
    const int T = gridDim.x * blockDim.x;

    #define CVT4(dst, src, n4)                                                  \
        for (int i = g; i < (n4); i += T) {                                     \
            float4 v = reinterpret_cast<const float4*>(src)[i];                 \
            __half2* o = reinterpret_cast<__half2*>(dst);                       \
            o[2*i]   = __floats2half2_rn(v.x, v.y);                             \
            o[2*i+1] = __floats2half2_rn(v.z, v.w);                             \
        }
    CVT4(g_xh,  x,  (NB*S_LEN*D_MODEL)/4)
    CVT4(g_Wqh, Wq, (D_MODEL*D_MODEL)/4)
    CVT4(g_Wkh, Wk, (D_MODEL*D_MODEL)/4)
    CVT4(g_Wvh, Wv, (D_MODEL*D_MODEL)/4)
    CVT4(g_Woh, Wo, (D_MODEL*D_MODEL)/4)
    #undef CVT4

    const float lam = lam_p[0] * LOG2E;
    for (int i = g; i < NH * HD * HD; i += T) {
        const int h = i >> 12, rem = i & 4095, e = rem >> 6, d = rem & 63;
        g_Jth[i] = __float2half(lam * J[(h << 12) + (d << 6) + e]);
    }
}

// ---------------------------------------------------------------------------
// Shared fp16 GEMM mainloop (champion, 3-stage compile-time pipeline).
// ---------------------------------------------------------------------------
__device__ __forceinline__ void mainloop_f16(
    const __half* __restrict__ Ag, const __half* __restrict__ Wg,
    uint32_t saA, uint32_t saW,
    int m0, int n0, int tid, int wm, int wn, int lane,
    float acc[4][4][4])
{
    const int mat = lane >> 3, r8 = lane & 7;
    const int crow = tid >> 2, ccc = (tid & 3) * 8;
    const size_t aG0 = (size_t)(m0 + crow)      * D_MODEL + ccc;
    const size_t aG1 = (size_t)(m0 + 64 + crow) * D_MODEL + ccc;
    const size_t wG0 = (size_t)(n0 + crow)      * D_MODEL + ccc;
    const size_t wG1 = (size_t)(n0 + 64 + crow) * D_MODEL + ccc;
    const uint32_t s0 = (crow * 40 + ccc) * 2;
    const uint32_t s1 = ((64 + crow) * 40 + ccc) * 2;

    const int aoff = ((mat & 1) * 8 + r8) * 40 + (mat >> 1) * 8;
    const int boff = ((mat >> 1) * 8 + r8) * 40 + (mat & 1) * 8;

    #define ISSUE_STAGE(ktile, buf) do {                                        \
        const int go_ = (ktile) * 32;                                           \
        const uint32_t sb_ = (uint32_t)(buf) * 10240u;                          \
        CP_ASYNC16(saA + sb_ + s0, Ag + aG0 + go_);                             \
        CP_ASYNC16(saA + sb_ + s1, Ag + aG1 + go_);                             \
        CP_ASYNC16(saW + sb_ + s0, Wg + wG0 + go_);                             \
        CP_ASYNC16(saW + sb_ + s1, Wg + wG1 + go_);                             \
        CP_COMMIT();                                                            \
    } while (0)

    ISSUE_STAGE(0, 0);
    ISSUE_STAGE(1, 1);

    #pragma unroll
    for (int kt = 0; kt < 32; kt++) {
        const int cbuf = kt % 3;
        if (kt < 31) { CP_WAIT1(); } else { CP_WAIT0(); }
        __syncthreads();
        if (kt + 2 < 32) ISSUE_STAGE(kt + 2, (kt + 2) % 3);

        const uint32_t ab = saA + (uint32_t)cbuf * 10240u;
        const uint32_t wb = saW + (uint32_t)cbuf * 10240u;

        #pragma unroll
        for (int ks = 0; ks < 32; ks += 16) {
            uint32_t af[4][4], bf[4][2];
            #pragma unroll
            for (int mt = 0; mt < 4; mt++)
                ldsm_x4(af[mt][0], af[mt][1], af[mt][2], af[mt][3],
                        ab + (uint32_t)(((wm + mt * 16) * 40 + aoff + ks) * 2));
            #pragma unroll
            for (int ntp = 0; ntp < 2; ntp++) {
                uint32_t b0, b1, b2, b3;
                ldsm_x4(b0, b1, b2, b3,
                        wb + (uint32_t)(((wn + ntp * 16) * 40 + boff + ks) * 2));
                bf[2*ntp][0]   = b0; bf[2*ntp][1]   = b1;
                bf[2*ntp+1][0] = b2; bf[2*ntp+1][1] = b3;
            }
            #pragma unroll
            for (int mt = 0; mt < 4; mt++)
                #pragma unroll
                for (int nt = 0; nt < 4; nt++)
                    mma_f16(acc[mt][nt], af[mt], bf[nt]);
        }
    }
    #undef ISSUE_STAGE
}

// ---------------------------------------------------------------------------
// QKV GEMM: z = 0 (Q + J-epilogue), 1 (K + tanh), 2 (V). 256 threads.
// ---------------------------------------------------------------------------
__global__ __launch_bounds__(256) void gemm_qkv(
    const __half* __restrict__ Ag,
    const __half* __restrict__ Wqh, const __half* __restrict__ Wkh,
    const __half* __restrict__ Wvh,
    const float* __restrict__ bq, const float* __restrict__ bk,
    const float* __restrict__ bv,
    const __half* __restrict__ Jtg,
    __half* __restrict__ Qh, __half* __restrict__ Kh, __half* __restrict__ Vh)
{
    extern __shared__ __half dsm[];
    __half* SA  = dsm;             // 3 x 5120
    __half* SW  = dsm + 15360;     // 3 x 5120
    __half* T   = dsm;             // 128 x 136 overlay (post-mainloop)
    __half* JtS = dsm + 30720;     // 2 x 64 x 72

    const int z    = blockIdx.z;
    const int tid  = threadIdx.x;
    const int lane = tid & 31;
    const int wid  = tid >> 5;
    const int m0   = blockIdx.y * 128;
    const int n0   = blockIdx.x * 128;
    const int wm   = (wid & 1) * 64;
    const int wn   = (wid >> 1) * 32;
    const int r    = lane >> 2;
    const int q    = lane & 3;
    const int mat  = lane >> 3, r8 = lane & 7;

    const __half* Wg = (z == 0) ? Wqh : (z == 1) ? Wkh : Wvh;
    const float* bias = (z == 0) ? bq : (z == 1) ? bk : bv;

    if (z == 0) {
        const int h0 = blockIdx.x * 2;
        for (int i = tid; i < 1024; i += 256) {
            const int row = i >> 3, cc = (i & 7) * 8;
            const int hh = row >> 6, e = row & 63;
            const uint4 v = *reinterpret_cast<const uint4*>(
                Jtg + ((size_t)(h0 + hh) << 12) + (e << 6) + cc);
            *reinterpret_cast<uint4*>(&JtS[(hh * 64 + e) * 72 + cc]) = v;
        }
    }

    float acc[4][4][4];
    #pragma unroll
    for (int i = 0; i < 4; i++)
        #pragma unroll
        for (int j = 0; j < 4; j++)
            #pragma unroll
            for (int e = 0; e < 4; e++) acc[i][j][e] = 0.f;

    mainloop_f16(Ag, Wg, smaddr(SA), smaddr(SW), m0, n0, tid, wm, wn, lane, acc);

    if (z == 0) __syncthreads();   // protect SA/SW before T overlay writes

    const float QSCALE = 0.125f * LOG2E;
    #pragma unroll
    for (int mt = 0; mt < 4; mt++) {
        #pragma unroll
        for (int nt = 0; nt < 4; nt++) {
            const int rl0 = wm + mt * 16 + r;
            const int cl  = wn + nt * 8 + 2 * q;
            const float2 bb = *reinterpret_cast<const float2*>(&bias[n0 + cl]);
            #pragma unroll
            for (int hh = 0; hh < 2; hh++) {
                const int rl = rl0 + hh * 8;
                const int rw = m0 + rl;
                const float v0 = acc[mt][nt][hh * 2]     + bb.x;
                const float v1 = acc[mt][nt][hh * 2 + 1] + bb.y;
                const int b = rw >> 11, s = rw & 2047;
                const int cg = n0 + cl;
                const int h = cg >> 6, hd = cg & 63;
                const size_t base = ((size_t)((b << 4) + h) * S_LEN + s);
                if (z == 0) {
                    *reinterpret_cast<__half2*>(&Qh[base * DQK + hd]) =
                        __floats2half2_rn(v0 * QSCALE, v1 * QSCALE);
                    *reinterpret_cast<__half2*>(&T[rl * 136 + cl]) =
                        __floats2half2_rn(tanhf(v0), tanhf(v1));
                } else if (z == 1) {
                    *reinterpret_cast<__half2*>(&Kh[base * DQK + hd]) =
                        __floats2half2_rn(v0, v1);
                    *reinterpret_cast<__half2*>(&Kh[base * DQK + 64 + hd]) =
                        __floats2half2_rn(tanhf(v0), tanhf(v1));
                } else {
                    *reinterpret_cast<__half2*>(&Vh[base * HD + hd]) =
                        __floats2half2_rn(v0, v1);
                }
            }
        }
    }

    if (z != 0) return;

    // J-epilogue: QJ[128x64 per head] = T[:, head] @ Jt[head]^T (k = 64)
    __syncthreads();
    const uint32_t tB  = smaddr(T);
    const uint32_t jB  = smaddr(JtS);
    const int aoffT = ((mat & 1) * 8 + r8) * 136 + (mat >> 1) * 8;
    const int boffJ = ((mat >> 1) * 8 + r8) * 72  + (mat & 1) * 8;

    #pragma unroll
    for (int hh2 = 0; hh2 < 2; hh2++) {
        float a2[8][4];
        #pragma unroll
        for (int nt = 0; nt < 8; nt++)
            #pragma unroll
            for (int e = 0; e < 4; e++) a2[nt][e] = 0.f;

        #pragma unroll
        for (int ks = 0; ks < 4; ks++) {
            uint32_t af[4];
            ldsm_x4(af[0], af[1], af[2], af[3],
                    tB + (uint32_t)((wid * 16 * 136 + aoffT + hh2 * 64 + ks * 16) * 2));
            #pragma unroll
            for (int ntp = 0; ntp < 4; ntp++) {
                uint32_t b0, b1, b2, b3;
                ldsm_x4(b0, b1, b2, b3,
                        jB + (uint32_t)((hh2 * 64 * 72 + ntp * 16 * 72 + boffJ + ks * 16) * 2));
                uint32_t bf0[2] = {b0, b1}, bf1[2] = {b2, b3};
                mma_f16(a2[2*ntp],   af, bf0);
                mma_f16(a2[2*ntp+1], af, bf1);
            }
        }

        const int hgl = blockIdx.x * 2 + hh2;
        #pragma unroll
        for (int nt = 0; nt < 8; nt++) {
            const int e0 = nt * 8 + 2 * q;
            #pragma unroll
            for (int hh = 0; hh < 2; hh++) {
                const int rw = m0 + wid * 16 + r + hh * 8;
                const int b = rw >> 11, s = rw & 2047;
                const size_t base = ((size_t)((b << 4) + hgl) * S_LEN + s);
                *reinterpret_cast<__half2*>(&Qh[base * DQK + 64 + e0]) =
                    __floats2half2_rn(a2[nt][hh * 2], a2[nt][hh * 2 + 1]);
            }
        }
    }
}

// ---------------------------------------------------------------------------
// Output GEMM: out[4096x1024] fp32 = attn_h @ Wo^T + bo. 256 threads.
// ---------------------------------------------------------------------------
__global__ __launch_bounds__(256) void gemm_out(
    const __half* __restrict__ Ag, const __half* __restrict__ Wg,
    const float* __restrict__ bias, float* __restrict__ C)
{
    extern __shared__ __half dsm[];
    __half* SA = dsm;
    __half* SW = dsm + 15360;

    const int tid  = threadIdx.x;
    const int lane = tid & 31;
    const int wid  = tid >> 5;
    const int m0   = blockIdx.y * 128;
    const int n0   = blockIdx.x * 128;
    const int wm   = (wid & 1) * 64;
    const int wn   = (wid >> 1) * 32;
    const int r    = lane >> 2;
    const int q    = lane & 3;

    float acc[4][4][4];
    #pragma unroll
    for (int i = 0; i < 4; i++)
        #pragma unroll
        for (int j = 0; j < 4; j++)
            #pragma unroll
            for (int e = 0; e < 4; e++) acc[i][j][e] = 0.f;

    mainloop_f16(Ag, Wg, smaddr(SA), smaddr(SW), m0, n0, tid, wm, wn, lane, acc);

    #pragma unroll
    for (int mt = 0; mt < 4; mt++) {
        #pragma unroll
        for (int nt = 0; nt < 4; nt++) {
            const int rw0 = m0 + wm + mt * 16 + r;
            const int cg  = n0 + wn + nt * 8 + 2 * q;
            const float2 bb = *reinterpret_cast<const float2*>(&bias[cg]);
            #pragma unroll
            for (int hh = 0; hh < 2; hh++) {
                const int rw = rw0 + hh * 8;
                *reinterpret_cast<float2*>(&C[(size_t)rw * D_MODEL + cg]) =
                    make_float2(acc[mt][nt][hh * 2] + bb.x,
                                acc[mt][nt][hh * 2 + 1] + bb.y);
            }
        }
    }
}

// ---------------------------------------------------------------------------
// Causal flash attention: fp16 mma + ldmatrix, double-buffered cp.async K/V.
// BR=128, BC=128 (halved softmax/sync count), 256 threads (8 warps, 16 rows).
// Scores already in log2 domain (Q pre-scaled) -> exp2f softmax.
// ---------------------------------------------------------------------------
__global__ __launch_bounds__(256) void flash_f16(
    const __half* __restrict__ Qh, const __half* __restrict__ Kh,
    const __half* __restrict__ Vh, __half* __restrict__ Out)
{
    extern __shared__ __half fsm[];
    const uint32_t ksB = smaddr(fsm);                 // 2 x 128*136 halves
    const uint32_t vsB = ksB + 2 * 128 * 136 * 2;     // 2 x 128*72 halves

    const int bh   = blockIdx.y;
    const int r0   = (int)(gridDim.x - 1 - blockIdx.x) * 128;  // heavy first
    const int tid  = threadIdx.x;
    const int lane = tid & 31;
    const int wid  = tid >> 5;
    const int slab = wid * 16;
    const int r    = lane >> 2;
    const int q    = lane & 3;
    const int lr8  = lane & 7, lm = lane >> 3;
    const int l16  = lane & 15, lh = lane >> 4;

    const __half* Qb = Qh + (size_t)bh * S_LEN * DQK;
    const __half* Kb = Kh + (size_t)bh * S_LEN * DQK;
    const __half* Vb = Vh + (size_t)bh * S_LEN * HD;

    // cp.async slots: K 128 rows x 128 halves = 8 chunks/thread;
    //                 V 128 rows x 64 halves  = 4 chunks/thread.
    const int kr0 = tid >> 1, kg0 = (tid & 1) * 64;
    const int vr0 = tid >> 1, vg0 = (tid & 1) * 32;

    #define ISSUE_TILE(c0_, buf_) do {                                          \
        const uint32_t kb_ = ksB + (uint32_t)(buf_) * (128 * 136 * 2);          \
        const uint32_t vb_ = vsB + (uint32_t)(buf_) * (128 * 72 * 2);           \
        const __half* ks_ = Kb + (size_t)(c0_) * DQK + kr0 * DQK + kg0;         \
        const __half* vs_ = Vb + (size_t)(c0_) * HD  + vr0 * HD  + vg0;         \
        const uint32_t kd_ = kb_ + (uint32_t)((kr0 * 136 + kg0) * 2);           \
        const uint32_t vd_ = vb_ + (uint32_t)((vr0 * 72  + vg0) * 2);           \
        CP_ASYNC16(kd_ +   0, ks_ +  0);                                        \
        CP_ASYNC16(kd_ +  16, ks_ +  8);                                        \
        CP_ASYNC16(kd_ +  32, ks_ + 16);                                        \
        CP_ASYNC16(kd_ +  48, ks_ + 24);                                        \
        CP_ASYNC16(kd_ +  64, ks_ + 32);                                        \
        CP_ASYNC16(kd_ +  80, ks_ + 40);                                        \
        CP_ASYNC16(kd_ +  96, ks_ + 48);                                        \
        CP_ASYNC16(kd_ + 112, ks_ + 56);                                        \
        CP_ASYNC16(vd_ +   0, vs_ +  0);                                        \
        CP_ASYNC16(vd_ +  16, vs_ +  8);                                        \
        CP_ASYNC16(vd_ +  32, vs_ + 16);                                        \
        CP_ASYNC16(vd_ +  48, vs_ + 24);                                        \
        CP_COMMIT();                                                            \
    } while (0)

    // Q fragments -> registers
    uint32_t qf[8][4];
    {
        const uint32_t* Qw = reinterpret_cast<const uint32_t*>(Qb);
        const int rowA = (r0 + slab + r) * 64;
        #pragma unroll
        for (int ks = 0; ks < 8; ks++) {
            const int c = ks * 8 + q;
            qf[ks][0] = Qw[rowA + c];
            qf[ks][1] = Qw[rowA + 512 + c];
            qf[ks][2] = Qw[rowA + c + 4];
            qf[ks][3] = Qw[rowA + 512 + c + 4];
        }
    }

    float m[2] = {-1e30f, -1e30f};
    float l[2] = {0.f, 0.f};
    float O[8][4];
    #pragma unroll
    for (int nt = 0; nt < 8; nt++)
        #pragma unroll
        for (int e = 0; e < 4; e++) O[nt][e] = 0.f;

    const int ntiles = (r0 >> 7) + 1;
    ISSUE_TILE(0, 0);

    for (int t = 0; t < ntiles; t++) {
        CP_WAIT0();
        __syncthreads();
        if (t + 1 < ntiles) ISSUE_TILE((t + 1) * 128, (t + 1) & 1);

        const int c0 = t * 128;
        const uint32_t kbuf = ksB + (uint32_t)(t & 1) * (128 * 136 * 2);
        const uint32_t vbuf = vsB + (uint32_t)(t & 1) * (128 * 72 * 2);

        if (c0 <= r0 + slab + 15) {
            // S = Q' K'^T  (16 x 128 per warp)
            float s[16][4];
            #pragma unroll
            for (int nt = 0; nt < 16; nt++)
                #pragma unroll
                for (int e = 0; e < 4; e++) s[nt][e] = 0.f;

            #pragma unroll
            for (int nt = 0; nt < 16; nt++) {
                #pragma unroll
                for (int kc = 0; kc < 4; kc++) {
                    uint32_t b0, b1, b2, b3;
                    ldsm_x4(b0, b1, b2, b3,
                            kbuf + (uint32_t)(((nt * 8 + lr8) * 136 + kc * 32 + lm * 8) * 2));
                    uint32_t bf0[2] = {b0, b1}, bf1[2] = {b2, b3};
                    mma_f16(s[nt], qf[kc * 2],     bf0);
                    mma_f16(s[nt], qf[kc * 2 + 1], bf1);
                }
            }

            if (c0 + 127 > r0 + slab) {
                #pragma unroll
                for (int nt = 0; nt < 16; nt++)
                    #pragma unroll
                    for (int e = 0; e < 4; e++) {
                        const int gr = r0 + slab + r + (e >> 1) * 8;
                        const int gc = c0 + nt * 8 + 2 * q + (e & 1);
                        if (gc > gr) s[nt][e] = -1e30f;
                    }
            }

            // online softmax (log2 domain)
            #pragma unroll
            for (int half = 0; half < 2; half++) {
                float mx = -1e30f;
                #pragma unroll
                for (int nt = 0; nt < 16; nt++)
                    mx = fmaxf(mx, fmaxf(s[nt][half * 2], s[nt][half * 2 + 1]));
                mx = fmaxf(mx, __shfl_xor_sync(0xffffffffu, mx, 1));
                mx = fmaxf(mx, __shfl_xor_sync(0xffffffffu, mx, 2));
                const float mn = fmaxf(m[half], mx);
                const float corr = exp2f(m[half] - mn);
                m[half] = mn;
                float rs = 0.f;
                #pragma unroll
                for (int nt = 0; nt < 16; nt++) {
                    const float p0 = exp2f(s[nt][half * 2]     - mn);
                    const float p1 = exp2f(s[nt][half * 2 + 1] - mn);
                    s[nt][half * 2]     = p0;
                    s[nt][half * 2 + 1] = p1;
                    rs += p0 + p1;
                }
                rs += __shfl_xor_sync(0xffffffffu, rs, 1);
                rs += __shfl_xor_sync(0xffffffffu, rs, 2);
                l[half] = l[half] * corr + rs;
                #pragma unroll
                for (int nt = 0; nt < 8; nt++) {
                    O[nt][half * 2]     *= corr;
                    O[nt][half * 2 + 1] *= corr;
                }
            }

            // P fragments (C->A identity): 8 k-chunks of 16 over BC=128
            uint32_t ap[8][4];
            #pragma unroll
            for (int j = 0; j < 8; j++) {
                ap[j][0] = packh2(s[2*j][0],   s[2*j][1]);
                ap[j][1] = packh2(s[2*j][2],   s[2*j][3]);
                ap[j][2] = packh2(s[2*j+1][0], s[2*j+1][1]);
                ap[j][3] = packh2(s[2*j+1][2], s[2*j+1][3]);
            }
            // O += P V  (V row-major [j][d], B frags via ldmatrix.trans)
            #pragma unroll
            for (int jc = 0; jc < 8; jc++) {
                #pragma unroll
                for (int nt2 = 0; nt2 < 4; nt2++) {
                    uint32_t b0, b1, b2, b3;
                    ldsm_x4_t(b0, b1, b2, b3,
                              vbuf + (uint32_t)(((jc * 16 + l16) * 72 + nt2 * 16 + lh * 8) * 2));
                    uint32_t bf0[2] = {b0, b1}, bf1[2] = {b2, b3};
                    mma_f16(O[2*nt2],     ap[jc], bf0);
                    mma_f16(O[2*nt2 + 1], ap[jc], bf1);
                }
            }
        }
    }
    #undef ISSUE_TILE

    // epilogue (fp16 out)
    const int b = bh >> 4, h = bh & 15;
    #pragma unroll
    for (int half = 0; half < 2; half++) {
        const float inv = 1.f / l[half];
        const int gr = r0 + slab + r + half * 8;
        #pragma unroll
        for (int nt = 0; nt < 8; nt++) {
            const int d0 = nt * 8 + 2 * q;
            *reinterpret_cast<__half2*>(
                Out + ((size_t)(b * S_LEN + gr)) * D_MODEL + h * HD + d0) =
                __floats2half2_rn(O[nt][half * 2] * inv, O[nt][half * 2 + 1] * inv);
        }
    }
}

// ---------------------------------------------------------------------------
extern "C" void kernel_launch(void* const* d_in, const int* in_sizes, int n_in,
                              void* d_out, int out_size)
{
    const float* x   = (const float*)d_in[0];
    const float* Wq  = (const float*)d_in[1];
    const float* bq  = (const float*)d_in[2];
    const float* Wk  = (const float*)d_in[3];
    const float* bk  = (const float*)d_in[4];
    const float* Wv  = (const float*)d_in[5];
    const float* bv  = (const float*)d_in[6];
    const float* Wo  = (const float*)d_in[7];
    const float* bo  = (const float*)d_in[8];
    const float* J   = (const float*)d_in[9];
    const float* lam = (const float*)d_in[10];
    float* out = (float*)d_out;

    __half *xh, *wqh, *wkh, *wvh, *woh, *jth, *qh, *kh, *vh, *ah;
    cudaGetSymbolAddress((void**)&xh,  g_xh);
    cudaGetSymbolAddress((void**)&wqh, g_Wqh);
    cudaGetSymbolAddress((void**)&wkh, g_Wkh);
    cudaGetSymbolAddress((void**)&wvh, g_Wvh);
    cudaGetSymbolAddress((void**)&woh, g_Woh);
    cudaGetSymbolAddress((void**)&jth, g_Jth);
    cudaGetSymbolAddress((void**)&qh,  g_Qh);
    cudaGetSymbolAddress((void**)&kh,  g_Kh);
    cudaGetSymbolAddress((void**)&vh,  g_Vh);
    cudaGetSymbolAddress((void**)&ah,  g_attnh);

    convert_kernel<<<296, 512>>>(x, Wq, Wk, Wv, Wo, J, lam);

    const int SM_QKV = (30720 + 9216) * 2;                         // 79872 B
    const int SM_OUT = 30720 * 2;                                  // 61440 B
    const int SM_FLA = (2 * 128 * 136 + 2 * 128 * 72) * 2;         // 106496 B
    cudaFuncSetAttribute(gemm_qkv, cudaFuncAttributeMaxDynamicSharedMemorySize, SM_QKV);
    cudaFuncSetAttribute(gemm_out, cudaFuncAttributeMaxDynamicSharedMemorySize, SM_OUT);
    cudaFuncSetAttribute(flash_f16, cudaFuncAttributeMaxDynamicSharedMemorySize, SM_FLA);

    gemm_qkv<<<dim3(8, 32, 3), 256, SM_QKV>>>(xh, wqh, wkh, wvh,
                                              bq, bk, bv, jth, qh, kh, vh);

    flash_f16<<<dim3(16, 32), 256, SM_FLA>>>(qh, kh, vh, ah);

    gemm_out<<<dim3(8, 32), 256, SM_OUT>>>(ah, woh, bo, out);
}

// round 16
// speedup vs baseline: 1.0522x; 1.0522x over previous
#include <cuda_runtime.h>
#include <cuda_fp16.h>
#include <cstdint>

#define D_MODEL 1024
#define S_LEN   2048
#define NB      2
#define NH      16
#define HD      64
#define DQK     128
#define BHN     (NB*NH)
#define LOG2E   1.44269504088896340736f

// Scratch (allocation-free rule: __device__ globals)
__device__ __half g_xh [(size_t)NB * S_LEN * D_MODEL];
__device__ __half g_Wqh[D_MODEL * D_MODEL];
__device__ __half g_Wkh[D_MODEL * D_MODEL];
__device__ __half g_Wvh[D_MODEL * D_MODEL];
__device__ __half g_Woh[D_MODEL * D_MODEL];
__device__ __half g_Jth[NH * HD * HD];              // [h][e][d] = lam*log2e * J[h][d][e]
__device__ __half g_Qh[(size_t)BHN * S_LEN * DQK];  // [0:64]=Q*(log2e/8), [64:128]=lam*log2e*tanh(Q)@J
__device__ __half g_Kh[(size_t)BHN * S_LEN * DQK];  // [0:64]=K,   [64:128]=tanh(K)
__device__ __half g_Vh[(size_t)BHN * S_LEN * HD];
__device__ __half g_attnh[(size_t)NB * S_LEN * D_MODEL];

__device__ __forceinline__ void mma_f16(float* c, const uint32_t* a, const uint32_t* b) {
    asm volatile(
        "mma.sync.aligned.m16n8k16.row.col.f32.f16.f16.f32 "
        "{%0,%1,%2,%3}, {%4,%5,%6,%7}, {%8,%9}, {%0,%1,%2,%3};"
        : "+f"(c[0]), "+f"(c[1]), "+f"(c[2]), "+f"(c[3])
        : "r"(a[0]), "r"(a[1]), "r"(a[2]), "r"(a[3]), "r"(b[0]), "r"(b[1]));
}

__device__ __forceinline__ uint32_t packh2(float x, float y) {
    __half2 h = __floats2half2_rn(x, y);
    return *reinterpret_cast<uint32_t*>(&h);
}

__device__ __forceinline__ uint32_t smaddr(const void* p) {
    uint32_t a;
    asm("{ .reg .u64 t; cvta.to.shared.u64 t, %1; cvt.u32.u64 %0, t; }"
        : "=r"(a) : "l"(p));
    return a;
}

__device__ __forceinline__ void ldsm_x4(uint32_t& r0, uint32_t& r1, uint32_t& r2,
                                        uint32_t& r3, uint32_t addr) {
    asm volatile("ldmatrix.sync.aligned.m8n8.x4.shared.b16 {%0,%1,%2,%3}, [%4];"
                 : "=r"(r0), "=r"(r1), "=r"(r2), "=r"(r3) : "r"(addr));
}

__device__ __forceinline__ void ldsm_x4_t(uint32_t& r0, uint32_t& r1, uint32_t& r2,
                                          uint32_t& r3, uint32_t addr) {
    asm volatile("ldmatrix.sync.aligned.m8n8.x4.trans.shared.b16 {%0,%1,%2,%3}, [%4];"
                 : "=r"(r0), "=r"(r1), "=r"(r2), "=r"(r3) : "r"(addr));
}

#define CP_ASYNC16(s, g) \
    asm volatile("cp.async.cg.shared.global [%0], [%1], 16;" :: "r"(s), "l"(g))
#define CP_COMMIT() asm volatile("cp.async.commit_group;")
#define CP_WAIT0()  asm volatile("cp.async.wait_group 0;")
#define CP_WAIT1()  asm volatile("cp.async.wait_group 1;")

// ---------------------------------------------------------------------------
// convert: fp32 inputs -> fp16 scratch; Jt[h][e][d] = lam*log2e * J[h][d][e]
// ---------------------------------------------------------------------------
__global__ void convert_kernel(
    const float* __restrict__ x,
    const float* __restrict__ Wq, const float* __restrict__ Wk,
    const float* __restrict__ Wv, const float* __restrict__ Wo,
    const float* __restrict__ J,  const float* __restrict__ lam_p)
{
    const int g = blockIdx.x * blockDim.x + threadIdx.x;
    const int T = gridDim.x * blockDim.x;

    #define CVT4(dst, src, n4)                                                  \
        for (int i = g; i < (n4); i += T) {                                     \
            float4 v = reinterpret_cast<const float4*>(src)[i];                 \
            __half2* o = reinterpret_cast<__half2*>(dst);                       \
            o[2*i]   = __floats2half2_rn(v.x, v.y);                             \
            o[2*i+1] = __floats2half2_rn(v.z, v.w);                             \
        }
    CVT4(g_xh,  x,  (NB*S_LEN*D_MODEL)/4)
    CVT4(g_Wqh, Wq, (D_MODEL*D_MODEL)/4)
    CVT4(g_Wkh, Wk, (D_MODEL*D_MODEL)/4)
    CVT4(g_Wvh, Wv, (D_MODEL*D_MODEL)/4)
    CVT4(g_Woh, Wo, (D_MODEL*D_MODEL)/4)
    #undef CVT4

    const float lam = lam_p[0] * LOG2E;
    for (int i = g; i < NH * HD * HD; i += T) {
        const int h = i >> 12, rem = i & 4095, e = rem >> 6, d = rem & 63;
        g_Jth[i] = __float2half(lam * J[(h << 12) + (d << 6) + e]);
    }
}

// ---------------------------------------------------------------------------
// Shared fp16 GEMM mainloop (champion, 3-stage compile-time pipeline).
// ---------------------------------------------------------------------------
__device__ __forceinline__ void mainloop_f16(
    const __half* __restrict__ Ag, const __half* __restrict__ Wg,
    uint32_t saA, uint32_t saW,
    int m0, int n0, int tid, int wm, int wn, int lane,
    float acc[4][4][4])
{
    const int mat = lane >> 3, r8 = lane & 7;
    const int crow = tid >> 2, ccc = (tid & 3) * 8;
    const size_t aG0 = (size_t)(m0 + crow)      * D_MODEL + ccc;
    const size_t aG1 = (size_t)(m0 + 64 + crow) * D_MODEL + ccc;
    const size_t wG0 = (size_t)(n0 + crow)      * D_MODEL + ccc;
    const size_t wG1 = (size_t)(n0 + 64 + crow) * D_MODEL + ccc;
    const uint32_t s0 = (crow * 40 + ccc) * 2;
    const uint32_t s1 = ((64 + crow) * 40 + ccc) * 2;

    const int aoff = ((mat & 1) * 8 + r8) * 40 + (mat >> 1) * 8;
    const int boff = ((mat >> 1) * 8 + r8) * 40 + (mat & 1) * 8;

    #define ISSUE_STAGE(ktile, buf) do {                                        \
        const int go_ = (ktile) * 32;                                           \
        const uint32_t sb_ = (uint32_t)(buf) * 10240u;                          \
        CP_ASYNC16(saA + sb_ + s0, Ag + aG0 + go_);                             \
        CP_ASYNC16(saA + sb_ + s1, Ag + aG1 + go_);                             \
        CP_ASYNC16(saW + sb_ + s0, Wg + wG0 + go_);                             \
        CP_ASYNC16(saW + sb_ + s1, Wg + wG1 + go_);                             \
        CP_COMMIT();                                                            \
    } while (0)

    ISSUE_STAGE(0, 0);
    ISSUE_STAGE(1, 1);

    #pragma unroll
    for (int kt = 0; kt < 32; kt++) {
        const int cbuf = kt % 3;
        if (kt < 31) { CP_WAIT1(); } else { CP_WAIT0(); }
        __syncthreads();
        if (kt + 2 < 32) ISSUE_STAGE(kt + 2, (kt + 2) % 3);

        const uint32_t ab = saA + (uint32_t)cbuf * 10240u;
        const uint32_t wb = saW + (uint32_t)cbuf * 10240u;

        #pragma unroll
        for (int ks = 0; ks < 32; ks += 16) {
            uint32_t af[4][4], bf[4][2];
            #pragma unroll
            for (int mt = 0; mt < 4; mt++)
                ldsm_x4(af[mt][0], af[mt][1], af[mt][2], af[mt][3],
                        ab + (uint32_t)(((wm + mt * 16) * 40 + aoff + ks) * 2));
            #pragma unroll
            for (int ntp = 0; ntp < 2; ntp++) {
                uint32_t b0, b1, b2, b3;
                ldsm_x4(b0, b1, b2, b3,
                        wb + (uint32_t)(((wn + ntp * 16) * 40 + boff + ks) * 2));
                bf[2*ntp][0]   = b0; bf[2*ntp][1]   = b1;
                bf[2*ntp+1][0] = b2; bf[2*ntp+1][1] = b3;
            }
            #pragma unroll
            for (int mt = 0; mt < 4; mt++)
                #pragma unroll
                for (int nt = 0; nt < 4; nt++)
                    mma_f16(acc[mt][nt], af[mt], bf[nt]);
        }
    }
    #undef ISSUE_STAGE
}

// ---------------------------------------------------------------------------
// QKV GEMM: z = 0 (Q + J-epilogue), 1 (K + tanh), 2 (V). 256 threads.
// ---------------------------------------------------------------------------
__global__ __launch_bounds__(256) void gemm_qkv(
    const __half* __restrict__ Ag,
    const __half* __restrict__ Wqh, const __half* __restrict__ Wkh,
    const __half* __restrict__ Wvh,
    const float* __restrict__ bq, const float* __restrict__ bk,
    const float* __restrict__ bv,
    const __half* __restrict__ Jtg,
    __half* __restrict__ Qh, __half* __restrict__ Kh, __half* __restrict__ Vh)
{
    extern __shared__ __half dsm[];
    __half* SA  = dsm;             // 3 x 5120
    __half* SW  = dsm + 15360;     // 3 x 5120
    __half* T   = dsm;             // 128 x 136 overlay (post-mainloop)
    __half* JtS = dsm + 30720;     // 2 x 64 x 72

    const int z    = blockIdx.z;
    const int tid  = threadIdx.x;
    const int lane = tid & 31;
    const int wid  = tid >> 5;
    const int m0   = blockIdx.y * 128;
    const int n0   = blockIdx.x * 128;
    const int wm   = (wid & 1) * 64;
    const int wn   = (wid >> 1) * 32;
    const int r    = lane >> 2;
    const int q    = lane & 3;
    const int mat  = lane >> 3, r8 = lane & 7;

    const __half* Wg = (z == 0) ? Wqh : (z == 1) ? Wkh : Wvh;
    const float* bias = (z == 0) ? bq : (z == 1) ? bk : bv;

    if (z == 0) {
        const int h0 = blockIdx.x * 2;
        for (int i = tid; i < 1024; i += 256) {
            const int row = i >> 3, cc = (i & 7) * 8;
            const int hh = row >> 6, e = row & 63;
            const uint4 v = *reinterpret_cast<const uint4*>(
                Jtg + ((size_t)(h0 + hh) << 12) + (e << 6) + cc);
            *reinterpret_cast<uint4*>(&JtS[(hh * 64 + e) * 72 + cc]) = v;
        }
    }

    float acc[4][4][4];
    #pragma unroll
    for (int i = 0; i < 4; i++)
        #pragma unroll
        for (int j = 0; j < 4; j++)
            #pragma unroll
            for (int e = 0; e < 4; e++) acc[i][j][e] = 0.f;

    mainloop_f16(Ag, Wg, smaddr(SA), smaddr(SW), m0, n0, tid, wm, wn, lane, acc);

    if (z == 0) __syncthreads();   // protect SA/SW before T overlay writes

    const float QSCALE = 0.125f * LOG2E;
    #pragma unroll
    for (int mt = 0; mt < 4; mt++) {
        #pragma unroll
        for (int nt = 0; nt < 4; nt++) {
            const int rl0 = wm + mt * 16 + r;
            const int cl  = wn + nt * 8 + 2 * q;
            const float2 bb = *reinterpret_cast<const float2*>(&bias[n0 + cl]);
            #pragma unroll
            for (int hh = 0; hh < 2; hh++) {
                const int rl = rl0 + hh * 8;
                const int rw = m0 + rl;
                const float v0 = acc[mt][nt][hh * 2]     + bb.x;
                const float v1 = acc[mt][nt][hh * 2 + 1] + bb.y;
                const int b = rw >> 11, s = rw & 2047;
                const int cg = n0 + cl;
                const int h = cg >> 6, hd = cg & 63;
                const size_t base = ((size_t)((b << 4) + h) * S_LEN + s);
                if (z == 0) {
                    *reinterpret_cast<__half2*>(&Qh[base * DQK + hd]) =
                        __floats2half2_rn(v0 * QSCALE, v1 * QSCALE);
                    *reinterpret_cast<__half2*>(&T[rl * 136 + cl]) =
                        __floats2half2_rn(tanhf(v0), tanhf(v1));
                } else if (z == 1) {
                    *reinterpret_cast<__half2*>(&Kh[base * DQK + hd]) =
                        __floats2half2_rn(v0, v1);
                    *reinterpret_cast<__half2*>(&Kh[base * DQK + 64 + hd]) =
                        __floats2half2_rn(tanhf(v0), tanhf(v1));
                } else {
                    *reinterpret_cast<__half2*>(&Vh[base * HD + hd]) =
                        __floats2half2_rn(v0, v1);
                }
            }
        }
    }

    if (z != 0) return;

    // J-epilogue: QJ[128x64 per head] = T[:, head] @ Jt[head]^T (k = 64)
    __syncthreads();
    const uint32_t tB  = smaddr(T);
    const uint32_t jB  = smaddr(JtS);
    const int aoffT = ((mat & 1) * 8 + r8) * 136 + (mat >> 1) * 8;
    const int boffJ = ((mat >> 1) * 8 + r8) * 72  + (mat & 1) * 8;

    #pragma unroll
    for (int hh2 = 0; hh2 < 2; hh2++) {
        float a2[8][4];
        #pragma unroll
        for (int nt = 0; nt < 8; nt++)
            #pragma unroll
            for (int e = 0; e < 4; e++) a2[nt][e] = 0.f;

        #pragma unroll
        for (int ks = 0; ks < 4; ks++) {
            uint32_t af[4];
            ldsm_x4(af[0], af[1], af[2], af[3],
                    tB + (uint32_t)((wid * 16 * 136 + aoffT + hh2 * 64 + ks * 16) * 2));
            #pragma unroll
            for (int ntp = 0; ntp < 4; ntp++) {
                uint32_t b0, b1, b2, b3;
                ldsm_x4(b0, b1, b2, b3,
                        jB + (uint32_t)((hh2 * 64 * 72 + ntp * 16 * 72 + boffJ + ks * 16) * 2));
                uint32_t bf0[2] = {b0, b1}, bf1[2] = {b2, b3};
                mma_f16(a2[2*ntp],   af, bf0);
                mma_f16(a2[2*ntp+1], af, bf1);
            }
        }

        const int hgl = blockIdx.x * 2 + hh2;
        #pragma unroll
        for (int nt = 0; nt < 8; nt++) {
            const int e0 = nt * 8 + 2 * q;
            #pragma unroll
            for (int hh = 0; hh < 2; hh++) {
                const int rw = m0 + wid * 16 + r + hh * 8;
                const int b = rw >> 11, s = rw & 2047;
                const size_t base = ((size_t)((b << 4) + hgl) * S_LEN + s);
                *reinterpret_cast<__half2*>(&Qh[base * DQK + 64 + e0]) =
                    __floats2half2_rn(a2[nt][hh * 2], a2[nt][hh * 2 + 1]);
            }
        }
    }
}

// ---------------------------------------------------------------------------
// Output GEMM: out[4096x1024] fp32 = attn_h @ Wo^T + bo. 256 threads.
// ---------------------------------------------------------------------------
__global__ __launch_bounds__(256) void gemm_out(
    const __half* __restrict__ Ag, const __half* __restrict__ Wg,
    const float* __restrict__ bias, float* __restrict__ C)
{
    extern __shared__ __half dsm[];
    __half* SA = dsm;
    __half* SW = dsm + 15360;

    const int tid  = threadIdx.x;
    const int lane = tid & 31;
    const int wid  = tid >> 5;
    const int m0   = blockIdx.y * 128;
    const int n0   = blockIdx.x * 128;
    const int wm   = (wid & 1) * 64;
    const int wn   = (wid >> 1) * 32;
    const int r    = lane >> 2;
    const int q    = lane & 3;

    float acc[4][4][4];
    #pragma unroll
    for (int i = 0; i < 4; i++)
        #pragma unroll
        for (int j = 0; j < 4; j++)
            #pragma unroll
            for (int e = 0; e < 4; e++) acc[i][j][e] = 0.f;

    mainloop_f16(Ag, Wg, smaddr(SA), smaddr(SW), m0, n0, tid, wm, wn, lane, acc);

    #pragma unroll
    for (int mt = 0; mt < 4; mt++) {
        #pragma unroll
        for (int nt = 0; nt < 4; nt++) {
            const int rw0 = m0 + wm + mt * 16 + r;
            const int cg  = n0 + wn + nt * 8 + 2 * q;
            const float2 bb = *reinterpret_cast<const float2*>(&bias[cg]);
            #pragma unroll
            for (int hh = 0; hh < 2; hh++) {
                const int rw = rw0 + hh * 8;
                *reinterpret_cast<float2*>(&C[(size_t)rw * D_MODEL + cg]) =
                    make_float2(acc[mt][nt][hh * 2] + bb.x,
                                acc[mt][nt][hh * 2 + 1] + bb.y);
            }
        }
    }
}

// ---------------------------------------------------------------------------
// Causal flash attention (champion BC=64 geometry, exp2-domain softmax).
// BR=128, BC=64, 256 threads (8 warps, 16 rows each).
// ---------------------------------------------------------------------------
__global__ __launch_bounds__(256) void flash_f16(
    const __half* __restrict__ Qh, const __half* __restrict__ Kh,
    const __half* __restrict__ Vh, __half* __restrict__ Out)
{
    extern __shared__ __half fsm[];
    const uint32_t ksB = smaddr(fsm);                 // 2 x 64*136 halves
    const uint32_t vsB = ksB + 2 * 64 * 136 * 2;      // 2 x 64*72 halves

    const int bh   = blockIdx.y;
    const int r0   = (int)(gridDim.x - 1 - blockIdx.x) * 128;  // heavy first
    const int tid  = threadIdx.x;
    const int lane = tid & 31;
    const int wid  = tid >> 5;
    const int slab = wid * 16;
    const int r    = lane >> 2;
    const int q    = lane & 3;
    const int lr8  = lane & 7, lm = lane >> 3;
    const int l16  = lane & 15, lh = lane >> 4;

    const __half* Qb = Qh + (size_t)bh * S_LEN * DQK;
    const __half* Kb = Kh + (size_t)bh * S_LEN * DQK;
    const __half* Vb = Vh + (size_t)bh * S_LEN * HD;

    const int kr0 = tid >> 2, kg0 = (tid & 3) * 8;
    const int vr0 = tid >> 2, vg0 = (tid & 3) * 16;

    #define ISSUE_TILE(c0_, buf_) do {                                          \
        const uint32_t kb_ = ksB + (uint32_t)(buf_) * (64 * 136 * 2);           \
        const uint32_t vb_ = vsB + (uint32_t)(buf_) * (64 * 72 * 2);            \
        const __half* ks_ = Kb + (size_t)(c0_) * DQK;                           \
        const __half* vs_ = Vb + (size_t)(c0_) * HD;                            \
        CP_ASYNC16(kb_ + (uint32_t)((kr0 * 136 + kg0) * 2),       ks_ + kr0 * DQK + kg0);      \
        CP_ASYNC16(kb_ + (uint32_t)((kr0 * 136 + kg0 + 32) * 2),  ks_ + kr0 * DQK + kg0 + 32); \
        CP_ASYNC16(kb_ + (uint32_t)((kr0 * 136 + kg0 + 64) * 2),  ks_ + kr0 * DQK + kg0 + 64); \
        CP_ASYNC16(kb_ + (uint32_t)((kr0 * 136 + kg0 + 96) * 2),  ks_ + kr0 * DQK + kg0 + 96); \
        CP_ASYNC16(vb_ + (uint32_t)((vr0 * 72 + vg0) * 2),        vs_ + vr0 * HD + vg0);       \
        CP_ASYNC16(vb_ + (uint32_t)((vr0 * 72 + vg0 + 8) * 2),    vs_ + vr0 * HD + vg0 + 8);   \
        CP_COMMIT();                                                            \
    } while (0)

    uint32_t qf[8][4];
    {
        const uint32_t* Qw = reinterpret_cast<const uint32_t*>(Qb);
        const int rowA = (r0 + slab + r) * 64;
        #pragma unroll
        for (int ks = 0; ks < 8; ks++) {
            const int c = ks * 8 + q;
            qf[ks][0] = Qw[rowA + c];
            qf[ks][1] = Qw[rowA + 512 + c];
            qf[ks][2] = Qw[rowA + c + 4];
            qf[ks][3] = Qw[rowA + 512 + c + 4];
        }
    }

    float m[2] = {-1e30f, -1e30f};
    float l[2] = {0.f, 0.f};
    float O[8][4];
    #pragma unroll
    for (int nt = 0; nt < 8; nt++)
        #pragma unroll
        for (int e = 0; e < 4; e++) O[nt][e] = 0.f;

    const int ntiles = (r0 >> 6) + 2;
    ISSUE_TILE(0, 0);

    for (int t = 0; t < ntiles; t++) {
        CP_WAIT0();
        __syncthreads();
        if (t + 1 < ntiles) ISSUE_TILE((t + 1) * 64, (t + 1) & 1);

        const int c0 = t * 64;
        const uint32_t kbuf = ksB + (uint32_t)(t & 1) * (64 * 136 * 2);
        const uint32_t vbuf = vsB + (uint32_t)(t & 1) * (64 * 72 * 2);

        if (c0 <= r0 + slab + 15) {
            float s[8][4];
            #pragma unroll
            for (int nt = 0; nt < 8; nt++)
                #pragma unroll
                for (int e = 0; e < 4; e++) s[nt][e] = 0.f;

            #pragma unroll
            for (int nt = 0; nt < 8; nt++) {
                #pragma unroll
                for (int kc = 0; kc < 4; kc++) {
                    uint32_t b0, b1, b2, b3;
                    ldsm_x4(b0, b1, b2, b3,
                            kbuf + (uint32_t)(((nt * 8 + lr8) * 136 + kc * 32 + lm * 8) * 2));
                    uint32_t bf0[2] = {b0, b1}, bf1[2] = {b2, b3};
                    mma_f16(s[nt], qf[kc * 2],     bf0);
                    mma_f16(s[nt], qf[kc * 2 + 1], bf1);
                }
            }

            if (c0 + 63 > r0 + slab) {
                #pragma unroll
                for (int nt = 0; nt < 8; nt++)
                    #pragma unroll
                    for (int e = 0; e < 4; e++) {
                        const int gr = r0 + slab + r + (e >> 1) * 8;
                        const int gc = c0 + nt * 8 + 2 * q + (e & 1);
                        if (gc > gr) s[nt][e] = -1e30f;
                    }
            }

            // online softmax (log2 domain)
            #pragma unroll
            for (int half = 0; half < 2; half++) {
                float mx = -1e30f;
                #pragma unroll
                for (int nt = 0; nt < 8; nt++)
                    mx = fmaxf(mx, fmaxf(s[nt][half * 2], s[nt][half * 2 + 1]));
                mx = fmaxf(mx, __shfl_xor_sync(0xffffffffu, mx, 1));
                mx = fmaxf(mx, __shfl_xor_sync(0xffffffffu, mx, 2));
                const float mn = fmaxf(m[half], mx);
                const float corr = exp2f(m[half] - mn);
                m[half] = mn;
                float rs = 0.f;
                #pragma unroll
                for (int nt = 0; nt < 8; nt++) {
                    const float p0 = exp2f(s[nt][half * 2]     - mn);
                    const float p1 = exp2f(s[nt][half * 2 + 1] - mn);
                    s[nt][half * 2]     = p0;
                    s[nt][half * 2 + 1] = p1;
                    rs += p0 + p1;
                }
                rs += __shfl_xor_sync(0xffffffffu, rs, 1);
                rs += __shfl_xor_sync(0xffffffffu, rs, 2);
                l[half] = l[half] * corr + rs;
                #pragma unroll
                for (int nt = 0; nt < 8; nt++) {
                    O[nt][half * 2]     *= corr;
                    O[nt][half * 2 + 1] *= corr;
                }
            }

            uint32_t ap[4][4];
            #pragma unroll
            for (int j = 0; j < 4; j++) {
                ap[j][0] = packh2(s[2*j][0],   s[2*j][1]);
                ap[j][1] = packh2(s[2*j][2],   s[2*j][3]);
                ap[j][2] = packh2(s[2*j+1][0], s[2*j+1][1]);
                ap[j][3] = packh2(s[2*j+1][2], s[2*j+1][3]);
            }
            #pragma unroll
            for (int jc = 0; jc < 4; jc++) {
                #pragma unroll
                for (int nt2 = 0; nt2 < 4; nt2++) {
                    uint32_t b0, b1, b2, b3;
                    ldsm_x4_t(b0, b1, b2, b3,
                              vbuf + (uint32_t)(((jc * 16 + l16) * 72 + nt2 * 16 + lh * 8) * 2));
                    uint32_t bf0[2] = {b0, b1}, bf1[2] = {b2, b3};
                    mma_f16(O[2*nt2],     ap[jc], bf0);
                    mma_f16(O[2*nt2 + 1], ap[jc], bf1);
                }
            }
        }
    }
    #undef ISSUE_TILE

    const int b = bh >> 4, h = bh & 15;
    #pragma unroll
    for (int half = 0; half < 2; half++) {
        const float inv = 1.f / l[half];
        const int gr = r0 + slab + r + half * 8;
        #pragma unroll
        for (int nt = 0; nt < 8; nt++) {
            const int d0 = nt * 8 + 2 * q;
            *reinterpret_cast<__half2*>(
                Out + ((size_t)(b * S_LEN + gr)) * D_MODEL + h * HD + d0) =
                __floats2half2_rn(O[nt][half * 2] * inv, O[nt][half * 2 + 1] * inv);
        }
    }
}

// ---------------------------------------------------------------------------
extern "C" void kernel_launch(void* const* d_in, const int* in_sizes, int n_in,
                              void* d_out, int out_size)
{
    const float* x   = (const float*)d_in[0];
    const float* Wq  = (const float*)d_in[1];
    const float* bq  = (const float*)d_in[2];
    const float* Wk  = (const float*)d_in[3];
    const float* bk  = (const float*)d_in[4];
    const float* Wv  = (const float*)d_in[5];
    const float* bv  = (const float*)d_in[6];
    const float* Wo  = (const float*)d_in[7];
    const float* bo  = (const float*)d_in[8];
    const float* J   = (const float*)d_in[9];
    const float* lam = (const float*)d_in[10];
    float* out = (float*)d_out;

    __half *xh, *wqh, *wkh, *wvh, *woh, *jth, *qh, *kh, *vh, *ah;
    cudaGetSymbolAddress((void**)&xh,  g_xh);
    cudaGetSymbolAddress((void**)&wqh, g_Wqh);
    cudaGetSymbolAddress((void**)&wkh, g_Wkh);
    cudaGetSymbolAddress((void**)&wvh, g_Wvh);
    cudaGetSymbolAddress((void**)&woh, g_Woh);
    cudaGetSymbolAddress((void**)&jth, g_Jth);
    cudaGetSymbolAddress((void**)&qh,  g_Qh);
    cudaGetSymbolAddress((void**)&kh,  g_Kh);
    cudaGetSymbolAddress((void**)&vh,  g_Vh);
    cudaGetSymbolAddress((void**)&ah,  g_attnh);

    convert_kernel<<<296, 512>>>(x, Wq, Wk, Wv, Wo, J, lam);

    const int SM_QKV = (30720 + 9216) * 2;                         // 79872 B
    const int SM_OUT = 30720 * 2;                                  // 61440 B
    const int SM_FLA = (2 * 64 * 136 + 2 * 64 * 72) * 2;           // 53248 B
    cudaFuncSetAttribute(gemm_qkv, cudaFuncAttributeMaxDynamicSharedMemorySize, SM_QKV);
    cudaFuncSetAttribute(gemm_out, cudaFuncAttributeMaxDynamicSharedMemorySize, SM_OUT);
    cudaFuncSetAttribute(flash_f16, cudaFuncAttributeMaxDynamicSharedMemorySize, SM_FLA);

    gemm_qkv<<<dim3(8, 32, 3), 256, SM_QKV>>>(xh, wqh, wkh, wvh,
                                              bq, bk, bv, jth, qh, kh, vh);

    flash_f16<<<dim3(16, 32), 256, SM_FLA>>>(qh, kh, vh, ah);

    gemm_out<<<dim3(8, 32), 256, SM_OUT>>>(ah, woh, bo, out);
}